// round 1
// baseline (speedup 1.0000x reference)
#include <cuda_runtime.h>
#include <cuda_bf16.h>
#include <cstdint>

#define TPB 256

// ---------------- packed f32x2 helpers (Blackwell FFMA2 path) ----------------
__device__ __forceinline__ unsigned long long fma2(unsigned long long a,
                                                   unsigned long long b,
                                                   unsigned long long c) {
    unsigned long long d;
    asm("fma.rn.f32x2 %0, %1, %2, %3;" : "=l"(d) : "l"(a), "l"(b), "l"(c));
    return d;
}
__device__ __forceinline__ unsigned long long add2(unsigned long long a,
                                                   unsigned long long b) {
    unsigned long long d;
    asm("add.rn.f32x2 %0, %1, %2;" : "=l"(d) : "l"(a), "l"(b));
    return d;
}
__device__ __forceinline__ unsigned long long pack2(float lo, float hi) {
    unsigned long long r;
    asm("mov.b64 %0, {%1, %2};" : "=l"(r) : "f"(lo), "f"(hi));
    return r;
}
__device__ __forceinline__ void unpack2(float& lo, float& hi, unsigned long long v) {
    asm("mov.b64 {%0, %1}, %2;" : "=f"(lo), "=f"(hi) : "l"(v));
}

// ---------------- smem layout (floats) ----------------
// Wq 1024 | Wk 1024 | Wv 1024 | W1 2048 | W2 2048 | WoutP 32x28=896 |
// tokE 27x36=972 | posE 8x36=288 | K 256x36=9216 | V 256x36=9216
static constexpr int OFF_WQ   = 0;
static constexpr int OFF_WK   = 1024;
static constexpr int OFF_WV   = 2048;
static constexpr int OFF_W1   = 3072;
static constexpr int OFF_W2   = 5120;
static constexpr int OFF_WOUT = 7168;
static constexpr int OFF_TOKE = 8064;
static constexpr int OFF_POSE = 9036;
static constexpr int OFF_K    = 9324;
static constexpr int OFF_V    = 18540;
static constexpr int SMEM_FLOATS = 27756;
static constexpr int SMEM_BYTES  = SMEM_FLOATS * 4;

// rank-32 mat-vec: acc[16] packed pairs over output dim; W row-major [32 x 32]
#define MATVEC32(acc, vec, Wsm)                                               \
    do {                                                                      \
        _Pragma("unroll") for (int _i = 0; _i < 16; _i++) acc[_i] = 0ULL;     \
        _Pragma("unroll") for (int _e = 0; _e < 32; _e++) {                   \
            unsigned long long _b = pack2((vec)[_e], (vec)[_e]);              \
            const ulonglong2* _w = (const ulonglong2*)((Wsm) + _e * 32);      \
            _Pragma("unroll") for (int _i = 0; _i < 8; _i++) {                \
                ulonglong2 _ww = _w[_i];                                      \
                acc[2 * _i]     = fma2(_b, _ww.x, acc[2 * _i]);               \
                acc[2 * _i + 1] = fma2(_b, _ww.y, acc[2 * _i + 1]);           \
            }                                                                 \
        }                                                                     \
    } while (0)

extern __shared__ float sm[];

__global__ void __launch_bounds__(TPB, 2)
mt_kernel(const int* __restrict__ tokens,
          const float* __restrict__ g_tokE, const float* __restrict__ g_posE,
          const float* __restrict__ g_Wq,  const float* __restrict__ g_Wk,
          const float* __restrict__ g_Wv,  const float* __restrict__ g_W1,
          const float* __restrict__ g_W2,  const float* __restrict__ g_Wout,
          float* __restrict__ g_out)
{
    float* s_Wq   = sm + OFF_WQ;
    float* s_Wk   = sm + OFF_WK;
    float* s_Wv   = sm + OFF_WV;
    float* s_W1   = sm + OFF_W1;
    float* s_W2   = sm + OFF_W2;
    float* s_Wout = sm + OFF_WOUT;
    float* s_tokE = sm + OFF_TOKE;
    float* s_posE = sm + OFF_POSE;
    float* s_K    = sm + OFF_K;
    float* s_V    = sm + OFF_V;

    const int tid = threadIdx.x;

    // ---- cooperative weight/embedding staging ----
    {
        int i = tid * 4;  // 256*4 == 1024: exactly one step for the 32x32 mats
        *(float4*)(s_Wq + i) = *(const float4*)(g_Wq + i);
        *(float4*)(s_Wk + i) = *(const float4*)(g_Wk + i);
        *(float4*)(s_Wv + i) = *(const float4*)(g_Wv + i);
        *(float4*)(s_W1 + i)        = *(const float4*)(g_W1 + i);
        *(float4*)(s_W1 + i + 1024) = *(const float4*)(g_W1 + i + 1024);
        *(float4*)(s_W2 + i)        = *(const float4*)(g_W2 + i);
        *(float4*)(s_W2 + i + 1024) = *(const float4*)(g_W2 + i + 1024);
    }
    for (int i = tid; i < 32 * 28; i += TPB) {
        int e = i / 28, c = i % 28;
        s_Wout[i] = (c < 27) ? g_Wout[e * 27 + c] : 0.0f;
    }
    for (int i = tid; i < 27 * 32; i += TPB) {
        int r = i >> 5, c = i & 31;
        s_tokE[r * 36 + c] = g_tokE[i];
    }
    for (int i = tid; i < 8 * 32; i += TPB) {
        int r = i >> 5, c = i & 31;
        s_posE[r * 36 + c] = g_posE[i];
    }
    __syncthreads();

    const int row = blockIdx.x * TPB + tid;  // global (b,t) row index
    const int t   = row & 7;
    const int tok = tokens[row];

    // ---- x = tok_emb[tok] + pos_emb[t] ----
    float x[32];
#pragma unroll
    for (int i = 0; i < 8; i++) {
        float4 a = *(const float4*)(s_tokE + tok * 36 + i * 4);
        float4 p = *(const float4*)(s_posE + t * 36 + i * 4);
        x[4 * i + 0] = a.x + p.x;
        x[4 * i + 1] = a.y + p.y;
        x[4 * i + 2] = a.z + p.z;
        x[4 * i + 3] = a.w + p.w;
    }

    // ---- K, V (staged to smem), Q (kept in regs) ----
    {
        unsigned long long kacc[16];
        MATVEC32(kacc, x, s_Wk);
        unsigned long long* kr = (unsigned long long*)(s_K + tid * 36);
#pragma unroll
        for (int i = 0; i < 16; i++) kr[i] = kacc[i];
    }
    {
        unsigned long long vacc[16];
        MATVEC32(vacc, x, s_Wv);
        unsigned long long* vr = (unsigned long long*)(s_V + tid * 36);
#pragma unroll
        for (int i = 0; i < 16; i++) vr[i] = vacc[i];
    }
    unsigned long long qacc[16];
    MATVEC32(qacc, x, s_Wq);
    __syncwarp();

    // ---- causal attention over T=8 (batch rows live in this warp) ----
    const int rowbase = tid & ~7;  // first row of this batch within block
    float sc[8], p[8];
    float m = -1e30f;
#pragma unroll
    for (int s = 0; s < 8; s++) {
        const unsigned long long* kr =
            (const unsigned long long*)(s_K + (rowbase + s) * 36);
        unsigned long long a0 = 0, a1 = 0, a2 = 0, a3 = 0;
#pragma unroll
        for (int i = 0; i < 16; i += 4) {
            a0 = fma2(qacc[i + 0], kr[i + 0], a0);
            a1 = fma2(qacc[i + 1], kr[i + 1], a1);
            a2 = fma2(qacc[i + 2], kr[i + 2], a2);
            a3 = fma2(qacc[i + 3], kr[i + 3], a3);
        }
        a0 = add2(add2(a0, a1), add2(a2, a3));
        float lo, hi;
        unpack2(lo, hi, a0);
        sc[s] = lo + hi;
        if (s <= t) m = fmaxf(m, sc[s]);
    }
    float ssum = 0.0f;
#pragma unroll
    for (int s = 0; s < 8; s++) {
        p[s] = (s <= t) ? __expf(sc[s] - m) : 0.0f;
        ssum += p[s];
    }
    const float inv = 1.0f / ssum;

    unsigned long long oacc[16];
#pragma unroll
    for (int i = 0; i < 16; i++) oacc[i] = 0ULL;
#pragma unroll
    for (int s = 0; s < 8; s++) {
        float a = p[s] * inv;
        unsigned long long aa = pack2(a, a);
        const ulonglong2* vr = (const ulonglong2*)(s_V + (rowbase + s) * 36);
#pragma unroll
        for (int i = 0; i < 8; i++) {
            ulonglong2 w = vr[i];
            oacc[2 * i]     = fma2(aa, w.x, oacc[2 * i]);
            oacc[2 * i + 1] = fma2(aa, w.y, oacc[2 * i + 1]);
        }
    }

    // ---- LN1(out + x) ----
    float n1[32];
#pragma unroll
    for (int i = 0; i < 16; i++) {
        float lo, hi;
        unpack2(lo, hi, oacc[i]);
        n1[2 * i]     = lo + x[2 * i];
        n1[2 * i + 1] = hi + x[2 * i + 1];
    }
    {
        float s1 = 0.0f, s2 = 0.0f;
#pragma unroll
        for (int e = 0; e < 32; e++) { s1 += n1[e]; s2 += n1[e] * n1[e]; }
        float mu  = s1 * (1.0f / 32.0f);
        float var = s2 * (1.0f / 32.0f) - mu * mu;
        float rs  = rsqrtf(var + 1e-5f);
#pragma unroll
        for (int e = 0; e < 32; e++) n1[e] = (n1[e] - mu) * rs;
    }

    // ---- MLP: y = relu(n1 @ W1) @ W2, processed in two 32-wide h halves ----
    unsigned long long yacc[16];
#pragma unroll
    for (int i = 0; i < 16; i++) yacc[i] = 0ULL;
#pragma unroll 1
    for (int half = 0; half < 2; half++) {
        unsigned long long hacc[16];
#pragma unroll
        for (int i = 0; i < 16; i++) hacc[i] = 0ULL;
#pragma unroll
        for (int e = 0; e < 32; e++) {
            unsigned long long b = pack2(n1[e], n1[e]);
            const ulonglong2* w =
                (const ulonglong2*)(s_W1 + e * 64 + half * 32);
#pragma unroll
            for (int i = 0; i < 8; i++) {
                ulonglong2 ww = w[i];
                hacc[2 * i]     = fma2(b, ww.x, hacc[2 * i]);
                hacc[2 * i + 1] = fma2(b, ww.y, hacc[2 * i + 1]);
            }
        }
#pragma unroll
        for (int jp = 0; jp < 16; jp++) {
            float h0, h1;
            unpack2(h0, h1, hacc[jp]);
            h0 = fmaxf(h0, 0.0f);
            h1 = fmaxf(h1, 0.0f);
            unsigned long long b0 = pack2(h0, h0), b1 = pack2(h1, h1);
            const ulonglong2* wa =
                (const ulonglong2*)(s_W2 + (half * 32 + 2 * jp) * 32);
            const ulonglong2* wb = wa + 8;  // next W2 row (32 floats)
#pragma unroll
            for (int i = 0; i < 8; i++) {
                ulonglong2 wwa = wa[i], wwb = wb[i];
                yacc[2 * i]     = fma2(b0, wwa.x, yacc[2 * i]);
                yacc[2 * i + 1] = fma2(b0, wwa.y, yacc[2 * i + 1]);
                yacc[2 * i]     = fma2(b1, wwb.x, yacc[2 * i]);
                yacc[2 * i + 1] = fma2(b1, wwb.y, yacc[2 * i + 1]);
            }
        }
    }

    // ---- LN2(y + n1) ----
    float n2[32];
#pragma unroll
    for (int i = 0; i < 16; i++) {
        float lo, hi;
        unpack2(lo, hi, yacc[i]);
        n2[2 * i]     = lo + n1[2 * i];
        n2[2 * i + 1] = hi + n1[2 * i + 1];
    }
    {
        float s1 = 0.0f, s2 = 0.0f;
#pragma unroll
        for (int e = 0; e < 32; e++) { s1 += n2[e]; s2 += n2[e] * n2[e]; }
        float mu  = s1 * (1.0f / 32.0f);
        float var = s2 * (1.0f / 32.0f) - mu * mu;
        float rs  = rsqrtf(var + 1e-5f);
#pragma unroll
        for (int e = 0; e < 32; e++) n2[e] = (n2[e] - mu) * rs;
    }

    // ---- logits = n2 @ Wout (padded to 28 cols, pad column is zero) ----
    unsigned long long lacc[14];
#pragma unroll
    for (int i = 0; i < 14; i++) lacc[i] = 0ULL;
#pragma unroll
    for (int e = 0; e < 32; e++) {
        unsigned long long b = pack2(n2[e], n2[e]);
        const ulonglong2* w = (const ulonglong2*)(s_Wout + e * 28);
#pragma unroll
        for (int i = 0; i < 7; i++) {
            ulonglong2 ww = w[i];
            lacc[2 * i]     = fma2(b, ww.x, lacc[2 * i]);
            lacc[2 * i + 1] = fma2(b, ww.y, lacc[2 * i + 1]);
        }
    }

    float* op = g_out + (size_t)row * 27;
#pragma unroll
    for (int i = 0; i < 13; i++) {
        float lo, hi;
        unpack2(lo, hi, lacc[i]);
        op[2 * i]     = lo;
        op[2 * i + 1] = hi;
    }
    {
        float lo, hi;
        unpack2(lo, hi, lacc[13]);
        op[26] = lo;
    }
}

extern "C" void kernel_launch(void* const* d_in, const int* in_sizes, int n_in,
                              void* d_out, int out_size) {
    const int*   tokens = (const int*)d_in[0];
    const float* tokE   = (const float*)d_in[1];
    const float* posE   = (const float*)d_in[2];
    const float* Wq     = (const float*)d_in[3];
    const float* Wk     = (const float*)d_in[4];
    const float* Wv     = (const float*)d_in[5];
    const float* W1     = (const float*)d_in[6];
    const float* W2     = (const float*)d_in[7];
    const float* Wout   = (const float*)d_in[8];
    float*       out    = (float*)d_out;

    cudaFuncSetAttribute(mt_kernel, cudaFuncAttributeMaxDynamicSharedMemorySize,
                         SMEM_BYTES);

    const int rows   = in_sizes[0];     // B*T = 1048576 (divisible by TPB)
    const int blocks = rows / TPB;
    mt_kernel<<<blocks, TPB, SMEM_BYTES>>>(tokens, tokE, posE, Wq, Wk, Wv, W1,
                                           W2, Wout, out);
}

// round 2
// speedup vs baseline: 1.2987x; 1.2987x over previous
#include <cuda_runtime.h>
#include <cuda_bf16.h>
#include <cstdint>

#define TPB 128
#define RPB 256   // rows per block (2 per thread)

// ---------------- packed f32x2 helpers (Blackwell FFMA2 path) ----------------
__device__ __forceinline__ unsigned long long fma2(unsigned long long a,
                                                   unsigned long long b,
                                                   unsigned long long c) {
    unsigned long long d;
    asm("fma.rn.f32x2 %0, %1, %2, %3;" : "=l"(d) : "l"(a), "l"(b), "l"(c));
    return d;
}
__device__ __forceinline__ unsigned long long add2(unsigned long long a,
                                                   unsigned long long b) {
    unsigned long long d;
    asm("add.rn.f32x2 %0, %1, %2;" : "=l"(d) : "l"(a), "l"(b));
    return d;
}
__device__ __forceinline__ unsigned long long pack2(float lo, float hi) {
    unsigned long long r;
    asm("mov.b64 %0, {%1, %2};" : "=l"(r) : "f"(lo), "f"(hi));
    return r;
}
__device__ __forceinline__ void unpack2(float& lo, float& hi, unsigned long long v) {
    asm("mov.b64 {%0, %1}, %2;" : "=f"(lo), "=f"(hi) : "l"(v));
}

// ---------------- smem layout (floats) ----------------
static constexpr int OFF_WQ   = 0;
static constexpr int OFF_WK   = 1024;
static constexpr int OFF_WV   = 2048;
static constexpr int OFF_W1   = 3072;
static constexpr int OFF_W2   = 5120;
static constexpr int OFF_WOUT = 7168;   // 32 x 28 padded
static constexpr int OFF_TOKE = 8064;   // 27 x 36
static constexpr int OFF_POSE = 9036;   // 8 x 36
static constexpr int OFF_K    = 9324;   // 256 x 36
static constexpr int OFF_V    = 18540;  // 256 x 36
static constexpr int SMEM_FLOATS = 27756;
static constexpr int SMEM_BYTES  = SMEM_FLOATS * 4;

// dual-row rank-32 matvec: one weight LDS.128 feeds 4 FFMA2
#define MATVEC32_DUAL(a0, a1, v0, v1, Wsm)                                    \
    do {                                                                      \
        _Pragma("unroll") for (int _i = 0; _i < 16; _i++) {                   \
            a0[_i] = 0ULL; a1[_i] = 0ULL;                                     \
        }                                                                     \
        _Pragma("unroll") for (int _e = 0; _e < 32; _e++) {                   \
            unsigned long long _b0 = pack2((v0)[_e], (v0)[_e]);               \
            unsigned long long _b1 = pack2((v1)[_e], (v1)[_e]);               \
            const ulonglong2* _w = (const ulonglong2*)((Wsm) + _e * 32);      \
            _Pragma("unroll") for (int _i = 0; _i < 8; _i++) {                \
                ulonglong2 _ww = _w[_i];                                      \
                a0[2 * _i]     = fma2(_b0, _ww.x, a0[2 * _i]);                \
                a0[2 * _i + 1] = fma2(_b0, _ww.y, a0[2 * _i + 1]);            \
                a1[2 * _i]     = fma2(_b1, _ww.x, a1[2 * _i]);                \
                a1[2 * _i + 1] = fma2(_b1, _ww.y, a1[2 * _i + 1]);            \
            }                                                                 \
        }                                                                     \
    } while (0)

extern __shared__ float sm[];

__device__ __forceinline__ void layernorm32(float* v) {
    float s1 = 0.0f, s2 = 0.0f;
#pragma unroll
    for (int e = 0; e < 32; e++) { s1 += v[e]; s2 += v[e] * v[e]; }
    float mu  = s1 * (1.0f / 32.0f);
    float var = s2 * (1.0f / 32.0f) - mu * mu;
    float rs  = rsqrtf(var + 1e-5f);
#pragma unroll
    for (int e = 0; e < 32; e++) v[e] = (v[e] - mu) * rs;
}

__global__ void __launch_bounds__(TPB, 2)
mt_kernel(const int* __restrict__ tokens,
          const float* __restrict__ g_tokE, const float* __restrict__ g_posE,
          const float* __restrict__ g_Wq,  const float* __restrict__ g_Wk,
          const float* __restrict__ g_Wv,  const float* __restrict__ g_W1,
          const float* __restrict__ g_W2,  const float* __restrict__ g_Wout,
          float* __restrict__ g_out)
{
    float* s_Wq   = sm + OFF_WQ;
    float* s_Wk   = sm + OFF_WK;
    float* s_Wv   = sm + OFF_WV;
    float* s_W1   = sm + OFF_W1;
    float* s_W2   = sm + OFF_W2;
    float* s_Wout = sm + OFF_WOUT;
    float* s_tokE = sm + OFF_TOKE;
    float* s_posE = sm + OFF_POSE;
    float* s_K    = sm + OFF_K;
    float* s_V    = sm + OFF_V;

    const int tid = threadIdx.x;

    // ---- cooperative weight/embedding staging ----
#pragma unroll
    for (int b = 0; b < 1024; b += TPB * 4) {
        int i = b + tid * 4;
        if (i < 1024) {
            *(float4*)(s_Wq + i) = *(const float4*)(g_Wq + i);
            *(float4*)(s_Wk + i) = *(const float4*)(g_Wk + i);
            *(float4*)(s_Wv + i) = *(const float4*)(g_Wv + i);
        }
    }
#pragma unroll
    for (int b = 0; b < 2048; b += TPB * 4) {
        int i = b + tid * 4;
        *(float4*)(s_W1 + i) = *(const float4*)(g_W1 + i);
        *(float4*)(s_W2 + i) = *(const float4*)(g_W2 + i);
    }
    for (int i = tid; i < 32 * 28; i += TPB) {
        int e = i / 28, c = i % 28;
        s_Wout[i] = (c < 27) ? g_Wout[e * 27 + c] : 0.0f;
    }
    for (int i = tid; i < 27 * 32; i += TPB) {
        int r = i >> 5, c = i & 31;
        s_tokE[r * 36 + c] = g_tokE[i];
    }
    for (int i = tid; i < 8 * 32; i += TPB) {
        int r = i >> 5, c = i & 31;
        s_posE[r * 36 + c] = g_posE[i];
    }
    __syncthreads();

    const int r0  = blockIdx.x * RPB + tid;  // first row for this thread
    const int r1  = r0 + TPB;                // second row
    const int t   = tid & 7;                 // same t for both rows
    const int tok0 = tokens[r0];
    const int tok1 = tokens[r1];

    // ---- x = tok_emb[tok] + pos_emb[t] ----
    float x0[32], x1[32];
#pragma unroll
    for (int i = 0; i < 8; i++) {
        float4 p  = *(const float4*)(s_posE + t * 36 + i * 4);
        float4 a0 = *(const float4*)(s_tokE + tok0 * 36 + i * 4);
        float4 a1 = *(const float4*)(s_tokE + tok1 * 36 + i * 4);
        x0[4 * i + 0] = a0.x + p.x;  x1[4 * i + 0] = a1.x + p.x;
        x0[4 * i + 1] = a0.y + p.y;  x1[4 * i + 1] = a1.y + p.y;
        x0[4 * i + 2] = a0.z + p.z;  x1[4 * i + 2] = a1.z + p.z;
        x0[4 * i + 3] = a0.w + p.w;  x1[4 * i + 3] = a1.w + p.w;
    }

    // ---- K, V staged to smem; Q kept in regs ----
    {
        unsigned long long k0[16], k1[16];
        MATVEC32_DUAL(k0, k1, x0, x1, s_Wk);
        unsigned long long* kr0 = (unsigned long long*)(s_K + tid * 36);
        unsigned long long* kr1 = (unsigned long long*)(s_K + (TPB + tid) * 36);
#pragma unroll
        for (int i = 0; i < 16; i++) { kr0[i] = k0[i]; kr1[i] = k1[i]; }
    }
    {
        unsigned long long v0[16], v1[16];
        MATVEC32_DUAL(v0, v1, x0, x1, s_Wv);
        unsigned long long* vr0 = (unsigned long long*)(s_V + tid * 36);
        unsigned long long* vr1 = (unsigned long long*)(s_V + (TPB + tid) * 36);
#pragma unroll
        for (int i = 0; i < 16; i++) { vr0[i] = v0[i]; vr1[i] = v1[i]; }
    }
    unsigned long long q0[16], q1[16];
    MATVEC32_DUAL(q0, q1, x0, x1, s_Wq);
    __syncwarp();   // K/V rows of a batch are produced+consumed within one warp

    // ---- causal attention over T=8, both rows ----
    const int rb0 = (tid & ~7) * 36;
    const int rb1 = (TPB + (tid & ~7)) * 36;
    float sc0[8], sc1[8];
#pragma unroll
    for (int s = 0; s < 8; s++) {
        const unsigned long long* ka =
            (const unsigned long long*)(s_K + rb0 + s * 36);
        const unsigned long long* kb =
            (const unsigned long long*)(s_K + rb1 + s * 36);
        unsigned long long a0 = 0, a1 = 0, b0 = 0, b1 = 0;
#pragma unroll
        for (int i = 0; i < 16; i += 2) {
            a0 = fma2(q0[i], ka[i], a0);
            a1 = fma2(q0[i + 1], ka[i + 1], a1);
            b0 = fma2(q1[i], kb[i], b0);
            b1 = fma2(q1[i + 1], kb[i + 1], b1);
        }
        a0 = add2(a0, a1);
        b0 = add2(b0, b1);
        float lo, hi;
        unpack2(lo, hi, a0); sc0[s] = lo + hi;
        unpack2(lo, hi, b0); sc1[s] = lo + hi;
    }
    float m0 = -1e30f, m1 = -1e30f;
#pragma unroll
    for (int s = 0; s < 8; s++) {
        if (s <= t) { m0 = fmaxf(m0, sc0[s]); m1 = fmaxf(m1, sc1[s]); }
    }
    float p0[8], p1[8];
    float sum0 = 0.0f, sum1 = 0.0f;
#pragma unroll
    for (int s = 0; s < 8; s++) {
        p0[s] = (s <= t) ? __expf(sc0[s] - m0) : 0.0f;
        p1[s] = (s <= t) ? __expf(sc1[s] - m1) : 0.0f;
        sum0 += p0[s]; sum1 += p1[s];
    }
    const float inv0 = 1.0f / sum0;
    const float inv1 = 1.0f / sum1;

    unsigned long long o0[16], o1[16];
#pragma unroll
    for (int i = 0; i < 16; i++) { o0[i] = 0ULL; o1[i] = 0ULL; }
#pragma unroll
    for (int s = 0; s < 8; s++) {
        float a = p0[s] * inv0;
        float b = p1[s] * inv1;
        unsigned long long aa = pack2(a, a);
        unsigned long long bb = pack2(b, b);
        const ulonglong2* va = (const ulonglong2*)(s_V + rb0 + s * 36);
        const ulonglong2* vb = (const ulonglong2*)(s_V + rb1 + s * 36);
#pragma unroll
        for (int i = 0; i < 8; i++) {
            ulonglong2 wa = va[i], wb = vb[i];
            o0[2 * i]     = fma2(aa, wa.x, o0[2 * i]);
            o0[2 * i + 1] = fma2(aa, wa.y, o0[2 * i + 1]);
            o1[2 * i]     = fma2(bb, wb.x, o1[2 * i]);
            o1[2 * i + 1] = fma2(bb, wb.y, o1[2 * i + 1]);
        }
    }

    // ---- LN1(out + x), both rows (n overwrites x storage conceptually) ----
    float n1a[32], n1b[32];
#pragma unroll
    for (int i = 0; i < 16; i++) {
        float lo, hi;
        unpack2(lo, hi, o0[i]);
        n1a[2 * i] = lo + x0[2 * i];  n1a[2 * i + 1] = hi + x0[2 * i + 1];
        unpack2(lo, hi, o1[i]);
        n1b[2 * i] = lo + x1[2 * i];  n1b[2 * i + 1] = hi + x1[2 * i + 1];
    }
    layernorm32(n1a);
    layernorm32(n1b);

    // ---- MLP: relu(n1 @ W1) @ W2, h processed in 4 chunks of 16 ----
    unsigned long long y0[16], y1[16];
#pragma unroll
    for (int i = 0; i < 16; i++) { y0[i] = 0ULL; y1[i] = 0ULL; }
#pragma unroll 1
    for (int c = 0; c < 4; c++) {
        unsigned long long h0[8], h1[8];
#pragma unroll
        for (int i = 0; i < 8; i++) { h0[i] = 0ULL; h1[i] = 0ULL; }
#pragma unroll
        for (int e = 0; e < 32; e++) {
            unsigned long long b0 = pack2(n1a[e], n1a[e]);
            unsigned long long b1 = pack2(n1b[e], n1b[e]);
            const ulonglong2* w = (const ulonglong2*)(s_W1 + e * 64 + c * 16);
#pragma unroll
            for (int i = 0; i < 4; i++) {
                ulonglong2 ww = w[i];
                h0[2 * i]     = fma2(b0, ww.x, h0[2 * i]);
                h0[2 * i + 1] = fma2(b0, ww.y, h0[2 * i + 1]);
                h1[2 * i]     = fma2(b1, ww.x, h1[2 * i]);
                h1[2 * i + 1] = fma2(b1, ww.y, h1[2 * i + 1]);
            }
        }
#pragma unroll
        for (int j = 0; j < 8; j++) {
            float ha0, ha1, hb0, hb1;
            unpack2(ha0, ha1, h0[j]);
            unpack2(hb0, hb1, h1[j]);
            ha0 = fmaxf(ha0, 0.0f); ha1 = fmaxf(ha1, 0.0f);
            hb0 = fmaxf(hb0, 0.0f); hb1 = fmaxf(hb1, 0.0f);
            const ulonglong2* wa =
                (const ulonglong2*)(s_W2 + (c * 16 + 2 * j) * 32);
            {
                unsigned long long pa = pack2(ha0, ha0);
                unsigned long long pb = pack2(hb0, hb0);
#pragma unroll
                for (int i = 0; i < 8; i++) {
                    ulonglong2 ww = wa[i];
                    y0[2 * i]     = fma2(pa, ww.x, y0[2 * i]);
                    y0[2 * i + 1] = fma2(pa, ww.y, y0[2 * i + 1]);
                    y1[2 * i]     = fma2(pb, ww.x, y1[2 * i]);
                    y1[2 * i + 1] = fma2(pb, ww.y, y1[2 * i + 1]);
                }
            }
            {
                unsigned long long pa = pack2(ha1, ha1);
                unsigned long long pb = pack2(hb1, hb1);
                const ulonglong2* wb = wa + 8;  // next W2 row
#pragma unroll
                for (int i = 0; i < 8; i++) {
                    ulonglong2 ww = wb[i];
                    y0[2 * i]     = fma2(pa, ww.x, y0[2 * i]);
                    y0[2 * i + 1] = fma2(pa, ww.y, y0[2 * i + 1]);
                    y1[2 * i]     = fma2(pb, ww.x, y1[2 * i]);
                    y1[2 * i + 1] = fma2(pb, ww.y, y1[2 * i + 1]);
                }
            }
        }
    }

    // ---- LN2(y + n1), both rows ----
    float n2a[32], n2b[32];
#pragma unroll
    for (int i = 0; i < 16; i++) {
        float lo, hi;
        unpack2(lo, hi, y0[i]);
        n2a[2 * i] = lo + n1a[2 * i];  n2a[2 * i + 1] = hi + n1a[2 * i + 1];
        unpack2(lo, hi, y1[i]);
        n2b[2 * i] = lo + n1b[2 * i];  n2b[2 * i + 1] = hi + n1b[2 * i + 1];
    }
    layernorm32(n2a);
    layernorm32(n2b);

    // ---- logits = n2 @ Wout (28-padded; col 27 is zero) ----
    unsigned long long l0[14], l1[14];
#pragma unroll
    for (int i = 0; i < 14; i++) { l0[i] = 0ULL; l1[i] = 0ULL; }
#pragma unroll
    for (int e = 0; e < 32; e++) {
        unsigned long long b0 = pack2(n2a[e], n2a[e]);
        unsigned long long b1 = pack2(n2b[e], n2b[e]);
        const ulonglong2* w = (const ulonglong2*)(s_Wout + e * 28);
#pragma unroll
        for (int i = 0; i < 7; i++) {
            ulonglong2 ww = w[i];
            l0[2 * i]     = fma2(b0, ww.x, l0[2 * i]);
            l0[2 * i + 1] = fma2(b0, ww.y, l0[2 * i + 1]);
            l1[2 * i]     = fma2(b1, ww.x, l1[2 * i]);
            l1[2 * i + 1] = fma2(b1, ww.y, l1[2 * i + 1]);
        }
    }

    // ---- stage outputs in smem (reuse s_K region), then coalesced STG ----
    __syncthreads();   // all K/V consumption finished block-wide
    float* s_out = s_K;  // 256*27 = 6912 floats <= 9216
    {
        float* oa = s_out + tid * 27;
        float* ob = s_out + (TPB + tid) * 27;
#pragma unroll
        for (int i = 0; i < 13; i++) {
            float lo, hi;
            unpack2(lo, hi, l0[i]); oa[2 * i] = lo; oa[2 * i + 1] = hi;
            unpack2(lo, hi, l1[i]); ob[2 * i] = lo; ob[2 * i + 1] = hi;
        }
        float lo, hi;
        unpack2(lo, hi, l0[13]); oa[26] = lo;
        unpack2(lo, hi, l1[13]); ob[26] = lo;
    }
    __syncthreads();
    {
        const float4* src = (const float4*)s_out;
        float4* dst = (float4*)(g_out + (size_t)blockIdx.x * RPB * 27);
        // 256*27 = 6912 floats = 1728 float4
#pragma unroll
        for (int b = 0; b < 1728; b += TPB) {
            int i = b + tid;
            if (i < 1728) dst[i] = src[i];
        }
    }
}

extern "C" void kernel_launch(void* const* d_in, const int* in_sizes, int n_in,
                              void* d_out, int out_size) {
    const int*   tokens = (const int*)d_in[0];
    const float* tokE   = (const float*)d_in[1];
    const float* posE   = (const float*)d_in[2];
    const float* Wq     = (const float*)d_in[3];
    const float* Wk     = (const float*)d_in[4];
    const float* Wv     = (const float*)d_in[5];
    const float* W1     = (const float*)d_in[6];
    const float* W2     = (const float*)d_in[7];
    const float* Wout   = (const float*)d_in[8];
    float*       out    = (float*)d_out;

    cudaFuncSetAttribute(mt_kernel, cudaFuncAttributeMaxDynamicSharedMemorySize,
                         SMEM_BYTES);

    const int rows   = in_sizes[0];   // B*T = 1048576
    const int blocks = rows / RPB;    // 4096
    mt_kernel<<<blocks, TPB, SMEM_BYTES>>>(tokens, tokE, posE, Wq, Wk, Wv, W1,
                                           W2, Wout, out);
}

// round 3
// speedup vs baseline: 1.4823x; 1.1414x over previous
#include <cuda_runtime.h>
#include <cuda_bf16.h>
#include <cstdint>

#define TPB 128
#define RPB 256   // rows per block (2 per thread)

// ---------------- packed f32x2 helpers (Blackwell FFMA2 path) ----------------
__device__ __forceinline__ unsigned long long fma2(unsigned long long a,
                                                   unsigned long long b,
                                                   unsigned long long c) {
    unsigned long long d;
    asm("fma.rn.f32x2 %0, %1, %2, %3;" : "=l"(d) : "l"(a), "l"(b), "l"(c));
    return d;
}
__device__ __forceinline__ unsigned long long add2(unsigned long long a,
                                                   unsigned long long b) {
    unsigned long long d;
    asm("add.rn.f32x2 %0, %1, %2;" : "=l"(d) : "l"(a), "l"(b));
    return d;
}
__device__ __forceinline__ unsigned long long pack2(float lo, float hi) {
    unsigned long long r;
    asm("mov.b64 %0, {%1, %2};" : "=l"(r) : "f"(lo), "f"(hi));
    return r;
}
__device__ __forceinline__ void unpack2(float& lo, float& hi, unsigned long long v) {
    asm("mov.b64 {%0, %1}, %2;" : "=f"(lo), "=f"(hi) : "l"(v));
}

// ---------------- smem layout (floats) ----------------
static constexpr int OFF_WQ   = 0;
static constexpr int OFF_WK   = 1024;
static constexpr int OFF_WV   = 2048;
static constexpr int OFF_W1   = 3072;
static constexpr int OFF_W2   = 5120;
static constexpr int OFF_WOUT = 7168;   // 32 x 28 padded
static constexpr int OFF_TOKE = 8064;   // 27 x 36
static constexpr int OFF_POSE = 9036;   // 8 x 36
static constexpr int OFF_KV   = 9324;   // 256 x 36 -- K, then reused for V, then out
static constexpr int SMEM_FLOATS = 18540;
static constexpr int SMEM_BYTES  = SMEM_FLOATS * 4;

// dual-row rank-32 matvec: one weight LDS.128 feeds 4 FFMA2
#define MATVEC32_DUAL(a0, a1, v0, v1, Wsm)                                    \
    do {                                                                      \
        _Pragma("unroll") for (int _i = 0; _i < 16; _i++) {                   \
            a0[_i] = 0ULL; a1[_i] = 0ULL;                                     \
        }                                                                     \
        _Pragma("unroll") for (int _e = 0; _e < 32; _e++) {                   \
            unsigned long long _b0 = pack2((v0)[_e], (v0)[_e]);               \
            unsigned long long _b1 = pack2((v1)[_e], (v1)[_e]);               \
            const ulonglong2* _w = (const ulonglong2*)((Wsm) + _e * 32);      \
            _Pragma("unroll") for (int _i = 0; _i < 8; _i++) {                \
                ulonglong2 _ww = _w[_i];                                      \
                a0[2 * _i]     = fma2(_b0, _ww.x, a0[2 * _i]);                \
                a0[2 * _i + 1] = fma2(_b0, _ww.y, a0[2 * _i + 1]);            \
                a1[2 * _i]     = fma2(_b1, _ww.x, a1[2 * _i]);                \
                a1[2 * _i + 1] = fma2(_b1, _ww.y, a1[2 * _i + 1]);            \
            }                                                                 \
        }                                                                     \
    } while (0)

extern __shared__ float sm[];

__device__ __forceinline__ void layernorm32(float* v) {
    float s1 = 0.0f, s2 = 0.0f;
#pragma unroll
    for (int e = 0; e < 32; e++) { s1 += v[e]; s2 += v[e] * v[e]; }
    float mu  = s1 * (1.0f / 32.0f);
    float var = s2 * (1.0f / 32.0f) - mu * mu;
    float rs  = rsqrtf(var + 1e-5f);
#pragma unroll
    for (int e = 0; e < 32; e++) v[e] = (v[e] - mu) * rs;
}

__global__ void __launch_bounds__(TPB, 3)
mt_kernel(const int* __restrict__ tokens,
          const float* __restrict__ g_tokE, const float* __restrict__ g_posE,
          const float* __restrict__ g_Wq,  const float* __restrict__ g_Wk,
          const float* __restrict__ g_Wv,  const float* __restrict__ g_W1,
          const float* __restrict__ g_W2,  const float* __restrict__ g_Wout,
          float* __restrict__ g_out)
{
    float* s_Wq   = sm + OFF_WQ;
    float* s_Wk   = sm + OFF_WK;
    float* s_Wv   = sm + OFF_WV;
    float* s_W1   = sm + OFF_W1;
    float* s_W2   = sm + OFF_W2;
    float* s_Wout = sm + OFF_WOUT;
    float* s_tokE = sm + OFF_TOKE;
    float* s_posE = sm + OFF_POSE;
    float* s_KV   = sm + OFF_KV;

    const int tid = threadIdx.x;

    // ---- cooperative weight/embedding staging ----
#pragma unroll
    for (int b = 0; b < 1024; b += TPB * 4) {
        int i = b + tid * 4;
        if (i < 1024) {
            *(float4*)(s_Wq + i) = *(const float4*)(g_Wq + i);
            *(float4*)(s_Wk + i) = *(const float4*)(g_Wk + i);
            *(float4*)(s_Wv + i) = *(const float4*)(g_Wv + i);
        }
    }
#pragma unroll
    for (int b = 0; b < 2048; b += TPB * 4) {
        int i = b + tid * 4;
        *(float4*)(s_W1 + i) = *(const float4*)(g_W1 + i);
        *(float4*)(s_W2 + i) = *(const float4*)(g_W2 + i);
    }
    for (int i = tid; i < 32 * 28; i += TPB) {
        int e = i / 28, c = i % 28;
        s_Wout[i] = (c < 27) ? g_Wout[e * 27 + c] : 0.0f;
    }
    for (int i = tid; i < 27 * 32; i += TPB) {
        int r = i >> 5, c = i & 31;
        s_tokE[r * 36 + c] = g_tokE[i];
    }
    for (int i = tid; i < 8 * 32; i += TPB) {
        int r = i >> 5, c = i & 31;
        s_posE[r * 36 + c] = g_posE[i];
    }
    __syncthreads();

    const int r0  = blockIdx.x * RPB + tid;  // first row for this thread
    const int r1  = r0 + TPB;                // second row
    const int t   = tid & 7;                 // same t for both rows
    const int tok0 = tokens[r0];
    const int tok1 = tokens[r1];

    // ---- x = tok_emb[tok] + pos_emb[t] ----
    float x0[32], x1[32];
#pragma unroll
    for (int i = 0; i < 8; i++) {
        float4 p  = *(const float4*)(s_posE + t * 36 + i * 4);
        float4 a0 = *(const float4*)(s_tokE + tok0 * 36 + i * 4);
        float4 a1 = *(const float4*)(s_tokE + tok1 * 36 + i * 4);
        x0[4 * i + 0] = a0.x + p.x;  x1[4 * i + 0] = a1.x + p.x;
        x0[4 * i + 1] = a0.y + p.y;  x1[4 * i + 1] = a1.y + p.y;
        x0[4 * i + 2] = a0.z + p.z;  x1[4 * i + 2] = a1.z + p.z;
        x0[4 * i + 3] = a0.w + p.w;  x1[4 * i + 3] = a1.w + p.w;
    }

    // ---- K into shared buffer (time-multiplexed K -> V) ----
    {
        unsigned long long k0[16], k1[16];
        MATVEC32_DUAL(k0, k1, x0, x1, s_Wk);
        ulonglong2* kr0 = (ulonglong2*)(s_KV + tid * 36);
        ulonglong2* kr1 = (ulonglong2*)(s_KV + (TPB + tid) * 36);
#pragma unroll
        for (int i = 0; i < 8; i++) {
            kr0[i] = make_ulonglong2(k0[2 * i], k0[2 * i + 1]);
            kr1[i] = make_ulonglong2(k1[2 * i], k1[2 * i + 1]);
        }
    }
    // Q in regs
    unsigned long long q0[16], q1[16];
    MATVEC32_DUAL(q0, q1, x0, x1, s_Wq);
    __syncwarp();   // K of this warp's batches visible

    // ---- scores (both rows) ----
    const int rb0 = (tid & ~7) * 36;
    const int rb1 = (TPB + (tid & ~7)) * 36;
    float p0[8], p1[8];   // scores, then probabilities in-place
#pragma unroll
    for (int s = 0; s < 8; s++) {
        const ulonglong2* ka = (const ulonglong2*)(s_KV + rb0 + s * 36);
        const ulonglong2* kb = (const ulonglong2*)(s_KV + rb1 + s * 36);
        unsigned long long a0 = 0, a1 = 0, b0 = 0, b1 = 0;
#pragma unroll
        for (int i = 0; i < 8; i++) {
            ulonglong2 kva = ka[i];
            ulonglong2 kvb = kb[i];
            a0 = fma2(q0[2 * i], kva.x, a0);
            a1 = fma2(q0[2 * i + 1], kva.y, a1);
            b0 = fma2(q1[2 * i], kvb.x, b0);
            b1 = fma2(q1[2 * i + 1], kvb.y, b1);
        }
        a0 = add2(a0, a1);
        b0 = add2(b0, b1);
        float lo, hi;
        unpack2(lo, hi, a0); p0[s] = lo + hi;
        unpack2(lo, hi, b0); p1[s] = lo + hi;
    }
    __syncwarp();   // all lanes done reading K before V overwrites buffer

    // ---- softmax (causal: s <= t) ----
    float m0 = -1e30f, m1 = -1e30f;
#pragma unroll
    for (int s = 0; s < 8; s++) {
        if (s <= t) { m0 = fmaxf(m0, p0[s]); m1 = fmaxf(m1, p1[s]); }
    }
    float sum0 = 0.0f, sum1 = 0.0f;
#pragma unroll
    for (int s = 0; s < 8; s++) {
        p0[s] = (s <= t) ? __expf(p0[s] - m0) : 0.0f;
        p1[s] = (s <= t) ? __expf(p1[s] - m1) : 0.0f;
        sum0 += p0[s]; sum1 += p1[s];
    }
    const float inv0 = 1.0f / sum0;
    const float inv1 = 1.0f / sum1;

    // ---- V into the SAME shared buffer ----
    {
        unsigned long long v0[16], v1[16];
        MATVEC32_DUAL(v0, v1, x0, x1, s_Wv);
        ulonglong2* vr0 = (ulonglong2*)(s_KV + tid * 36);
        ulonglong2* vr1 = (ulonglong2*)(s_KV + (TPB + tid) * 36);
#pragma unroll
        for (int i = 0; i < 8; i++) {
            vr0[i] = make_ulonglong2(v0[2 * i], v0[2 * i + 1]);
            vr1[i] = make_ulonglong2(v1[2 * i], v1[2 * i + 1]);
        }
    }
    __syncwarp();   // V visible

    // ---- out = attn @ V ----
    unsigned long long o0[16], o1[16];
#pragma unroll
    for (int i = 0; i < 16; i++) { o0[i] = 0ULL; o1[i] = 0ULL; }
#pragma unroll
    for (int s = 0; s < 8; s++) {
        float a = p0[s] * inv0;
        float b = p1[s] * inv1;
        unsigned long long aa = pack2(a, a);
        unsigned long long bb = pack2(b, b);
        const ulonglong2* va = (const ulonglong2*)(s_KV + rb0 + s * 36);
        const ulonglong2* vb = (const ulonglong2*)(s_KV + rb1 + s * 36);
#pragma unroll
        for (int i = 0; i < 8; i++) {
            ulonglong2 wa = va[i], wb = vb[i];
            o0[2 * i]     = fma2(aa, wa.x, o0[2 * i]);
            o0[2 * i + 1] = fma2(aa, wa.y, o0[2 * i + 1]);
            o1[2 * i]     = fma2(bb, wb.x, o1[2 * i]);
            o1[2 * i + 1] = fma2(bb, wb.y, o1[2 * i + 1]);
        }
    }

    // ---- LN1(out + x) ----
    float n1a[32], n1b[32];
#pragma unroll
    for (int i = 0; i < 16; i++) {
        float lo, hi;
        unpack2(lo, hi, o0[i]);
        n1a[2 * i] = lo + x0[2 * i];  n1a[2 * i + 1] = hi + x0[2 * i + 1];
        unpack2(lo, hi, o1[i]);
        n1b[2 * i] = lo + x1[2 * i];  n1b[2 * i + 1] = hi + x1[2 * i + 1];
    }
    layernorm32(n1a);
    layernorm32(n1b);

    // ---- MLP: relu(n1 @ W1) @ W2, h in 8 chunks of 8 (low reg pressure) ----
    unsigned long long y0[16], y1[16];
#pragma unroll
    for (int i = 0; i < 16; i++) { y0[i] = 0ULL; y1[i] = 0ULL; }
#pragma unroll 1
    for (int c = 0; c < 8; c++) {
        unsigned long long h0[4], h1[4];
#pragma unroll
        for (int i = 0; i < 4; i++) { h0[i] = 0ULL; h1[i] = 0ULL; }
#pragma unroll
        for (int e = 0; e < 32; e++) {
            unsigned long long b0 = pack2(n1a[e], n1a[e]);
            unsigned long long b1 = pack2(n1b[e], n1b[e]);
            const ulonglong2* w = (const ulonglong2*)(s_W1 + e * 64 + c * 8);
#pragma unroll
            for (int i = 0; i < 2; i++) {
                ulonglong2 ww = w[i];
                h0[2 * i]     = fma2(b0, ww.x, h0[2 * i]);
                h0[2 * i + 1] = fma2(b0, ww.y, h0[2 * i + 1]);
                h1[2 * i]     = fma2(b1, ww.x, h1[2 * i]);
                h1[2 * i + 1] = fma2(b1, ww.y, h1[2 * i + 1]);
            }
        }
#pragma unroll
        for (int j = 0; j < 4; j++) {
            float ha0, ha1, hb0, hb1;
            unpack2(ha0, ha1, h0[j]);
            unpack2(hb0, hb1, h1[j]);
            ha0 = fmaxf(ha0, 0.0f); ha1 = fmaxf(ha1, 0.0f);
            hb0 = fmaxf(hb0, 0.0f); hb1 = fmaxf(hb1, 0.0f);
            const ulonglong2* wa =
                (const ulonglong2*)(s_W2 + (c * 8 + 2 * j) * 32);
            {
                unsigned long long pa = pack2(ha0, ha0);
                unsigned long long pb = pack2(hb0, hb0);
#pragma unroll
                for (int i = 0; i < 8; i++) {
                    ulonglong2 ww = wa[i];
                    y0[2 * i]     = fma2(pa, ww.x, y0[2 * i]);
                    y0[2 * i + 1] = fma2(pa, ww.y, y0[2 * i + 1]);
                    y1[2 * i]     = fma2(pb, ww.x, y1[2 * i]);
                    y1[2 * i + 1] = fma2(pb, ww.y, y1[2 * i + 1]);
                }
            }
            {
                unsigned long long pa = pack2(ha1, ha1);
                unsigned long long pb = pack2(hb1, hb1);
                const ulonglong2* wb = wa + 8;  // next W2 row
#pragma unroll
                for (int i = 0; i < 8; i++) {
                    ulonglong2 ww = wb[i];
                    y0[2 * i]     = fma2(pa, ww.x, y0[2 * i]);
                    y0[2 * i + 1] = fma2(pa, ww.y, y0[2 * i + 1]);
                    y1[2 * i]     = fma2(pb, ww.x, y1[2 * i]);
                    y1[2 * i + 1] = fma2(pb, ww.y, y1[2 * i + 1]);
                }
            }
        }
    }

    // ---- LN2(y + n1) ----
    float n2a[32], n2b[32];
#pragma unroll
    for (int i = 0; i < 16; i++) {
        float lo, hi;
        unpack2(lo, hi, y0[i]);
        n2a[2 * i] = lo + n1a[2 * i];  n2a[2 * i + 1] = hi + n1a[2 * i + 1];
        unpack2(lo, hi, y1[i]);
        n2b[2 * i] = lo + n1b[2 * i];  n2b[2 * i + 1] = hi + n1b[2 * i + 1];
    }
    layernorm32(n2a);
    layernorm32(n2b);

    // ---- logits = n2 @ Wout (28-padded; col 27 is zero) ----
    unsigned long long l0[14], l1[14];
#pragma unroll
    for (int i = 0; i < 14; i++) { l0[i] = 0ULL; l1[i] = 0ULL; }
#pragma unroll
    for (int e = 0; e < 32; e++) {
        unsigned long long b0 = pack2(n2a[e], n2a[e]);
        unsigned long long b1 = pack2(n2b[e], n2b[e]);
        const ulonglong2* w = (const ulonglong2*)(s_Wout + e * 28);
#pragma unroll
        for (int i = 0; i < 7; i++) {
            ulonglong2 ww = w[i];
            l0[2 * i]     = fma2(b0, ww.x, l0[2 * i]);
            l0[2 * i + 1] = fma2(b0, ww.y, l0[2 * i + 1]);
            l1[2 * i]     = fma2(b1, ww.x, l1[2 * i]);
            l1[2 * i + 1] = fma2(b1, ww.y, l1[2 * i + 1]);
        }
    }

    // ---- stage outputs in smem (reuse KV buffer), then coalesced STG ----
    __syncthreads();   // all warps done with their KV region
    float* s_out = s_KV;  // 256*27 = 6912 floats <= 9216
    {
        float* oa = s_out + tid * 27;
        float* ob = s_out + (TPB + tid) * 27;
#pragma unroll
        for (int i = 0; i < 13; i++) {
            float lo, hi;
            unpack2(lo, hi, l0[i]); oa[2 * i] = lo; oa[2 * i + 1] = hi;
            unpack2(lo, hi, l1[i]); ob[2 * i] = lo; ob[2 * i + 1] = hi;
        }
        float lo, hi;
        unpack2(lo, hi, l0[13]); oa[26] = lo;
        unpack2(lo, hi, l1[13]); ob[26] = lo;
    }
    __syncthreads();
    {
        const float4* src = (const float4*)s_out;
        float4* dst = (float4*)(g_out + (size_t)blockIdx.x * RPB * 27);
        // 256*27 = 6912 floats = 1728 float4
#pragma unroll
        for (int b = 0; b < 1728; b += TPB) {
            int i = b + tid;
            if (i < 1728) dst[i] = src[i];
        }
    }
}

extern "C" void kernel_launch(void* const* d_in, const int* in_sizes, int n_in,
                              void* d_out, int out_size) {
    const int*   tokens = (const int*)d_in[0];
    const float* tokE   = (const float*)d_in[1];
    const float* posE   = (const float*)d_in[2];
    const float* Wq     = (const float*)d_in[3];
    const float* Wk     = (const float*)d_in[4];
    const float* Wv     = (const float*)d_in[5];
    const float* W1     = (const float*)d_in[6];
    const float* W2     = (const float*)d_in[7];
    const float* Wout   = (const float*)d_in[8];
    float*       out    = (float*)d_out;

    cudaFuncSetAttribute(mt_kernel, cudaFuncAttributeMaxDynamicSharedMemorySize,
                         SMEM_BYTES);

    const int rows   = in_sizes[0];   // B*T = 1048576
    const int blocks = rows / RPB;    // 4096
    mt_kernel<<<blocks, TPB, SMEM_BYTES>>>(tokens, tokE, posE, Wq, Wk, Wv, W1,
                                           W2, Wout, out);
}